// round 1
// baseline (speedup 1.0000x reference)
#include <cuda_runtime.h>
#include <math.h>

#define HH 8
#define HD 32
#define BB 4
#define NN 2048
#define DD 256
#define BH (BB*HH)   // 32

// ---- device scratch (static: allocation-free rule) ----
__device__ float g_Q[(size_t)BH*NN*HD];
__device__ float g_K[(size_t)BH*NN*HD];
__device__ float g_P[(size_t)BH*NN*NN];     // unnormalized exp(S), 512 MB
__device__ float g_rowsum[BH*NN];
__device__ float g_t0[(size_t)BH*NN*HD];
__device__ float g_t1[(size_t)BH*NN*HD];
__device__ float g_acc[(size_t)BH*NN*HD];

// ============================================================
// Kernel 1: QKV projection + head split.
// grid (128, 4, 3): 64-row x 64-col tiles, z = which matrix.
// ============================================================
__global__ void qkv_kernel(const float* __restrict__ x,
                           const float* __restrict__ Wq, const float* __restrict__ bq,
                           const float* __restrict__ Wk, const float* __restrict__ bk,
                           const float* __restrict__ Wv, const float* __restrict__ bv,
                           const float* __restrict__ coeffs) {
    const int mat = blockIdx.z;
    const float* W    = (mat == 0) ? Wq : ((mat == 1) ? Wk : Wv);
    const float* bias = (mat == 0) ? bq : ((mat == 1) ? bk : bv);
    const int m0 = blockIdx.x * 64;
    const int c0 = blockIdx.y * 64;

    __shared__ float Xs[64][33];
    __shared__ float Ws[32][64];

    const int tid = threadIdx.x;
    const int ty = tid >> 4, tx = tid & 15;

    float acc[4][4] = {};

    for (int k0 = 0; k0 < DD; k0 += 32) {
        for (int l = tid; l < 512; l += 256) {
            int r = l >> 3, kq = l & 7;
            float4 v = *(const float4*)(x + (size_t)(m0 + r) * DD + k0 + kq * 4);
            Xs[r][kq*4+0] = v.x; Xs[r][kq*4+1] = v.y;
            Xs[r][kq*4+2] = v.z; Xs[r][kq*4+3] = v.w;
        }
        for (int l = tid; l < 512; l += 256) {
            int k = l >> 4, cq = l & 15;
            *(float4*)&Ws[k][cq*4] = *(const float4*)(W + (size_t)(k0 + k) * DD + c0 + cq * 4);
        }
        __syncthreads();
        #pragma unroll
        for (int kk = 0; kk < 32; kk++) {
            float a0 = Xs[ty*4+0][kk];
            float a1 = Xs[ty*4+1][kk];
            float a2 = Xs[ty*4+2][kk];
            float a3 = Xs[ty*4+3][kk];
            float4 b = *(float4*)&Ws[kk][tx*4];
            acc[0][0] += a0*b.x; acc[0][1] += a0*b.y; acc[0][2] += a0*b.z; acc[0][3] += a0*b.w;
            acc[1][0] += a1*b.x; acc[1][1] += a1*b.y; acc[1][2] += a1*b.z; acc[1][3] += a1*b.w;
            acc[2][0] += a2*b.x; acc[2][1] += a2*b.y; acc[2][2] += a2*b.z; acc[2][3] += a2*b.w;
            acc[3][0] += a3*b.x; acc[3][1] += a3*b.y; acc[3][2] += a3*b.z; acc[3][3] += a3*b.w;
        }
        __syncthreads();
    }

    #pragma unroll
    for (int i = 0; i < 4; i++) {
        int m = m0 + ty * 4 + i;
        int b_ = m >> 11, n = m & 2047;
        #pragma unroll
        for (int j = 0; j < 4; j++) {
            int c = c0 + tx * 4 + j;
            float val = acc[i][j] + bias[c];
            int h = c >> 5, d = c & 31;
            size_t idx = ((size_t)(b_ * HH + h) * NN + n) * HD + d;
            if (mat == 0)      g_Q[idx] = val;
            else if (mat == 1) g_K[idx] = val;
            else {
                g_t0[idx]  = val;
                g_acc[idx] = coeffs[h * 4] * val;   // c0 * v
            }
        }
    }
}

// ============================================================
// Kernel 2: P = exp(Q K^T * scale) + rowsums (no normalization).
// grid (16 row-tiles, 32 bh), block 256, 8x8 microtile over 128x128.
// ============================================================
__global__ void attnP_kernel() {
    const int bh = blockIdx.y;
    const int r0 = blockIdx.x * 128;

    __shared__ float Qt[HD][132];   // transposed: Qt[k][row], stride 132 keeps LDS.128 aligned
    __shared__ float Kt[HD][132];
    __shared__ float s_rowsum[128];

    const int tid = threadIdx.x;
    const int ty = tid >> 4, tx = tid & 15;

    const float* Qb = g_Q + (size_t)bh * NN * HD + (size_t)r0 * HD;
    for (int l = tid; l < 1024; l += 256) {       // 128 rows * 8 float4
        int r = l >> 3, kq = l & 7;
        float4 v = *(const float4*)(Qb + (size_t)r * HD + kq * 4);
        Qt[kq*4+0][r] = v.x; Qt[kq*4+1][r] = v.y;
        Qt[kq*4+2][r] = v.z; Qt[kq*4+3][r] = v.w;
    }
    if (tid < 128) s_rowsum[tid] = 0.f;
    __syncthreads();

    const float scale = 0.17677669529663687f;     // 1/sqrt(32)

    for (int ct = 0; ct < 16; ct++) {
        int c0 = ct * 128;
        const float* Kb = g_K + (size_t)bh * NN * HD + (size_t)c0 * HD;
        for (int l = tid; l < 1024; l += 256) {
            int r = l >> 3, kq = l & 7;
            float4 v = *(const float4*)(Kb + (size_t)r * HD + kq * 4);
            Kt[kq*4+0][r] = v.x; Kt[kq*4+1][r] = v.y;
            Kt[kq*4+2][r] = v.z; Kt[kq*4+3][r] = v.w;
        }
        __syncthreads();

        float acc[8][8] = {};
        #pragma unroll
        for (int kk = 0; kk < HD; kk++) {
            float4 a0 = *(float4*)&Qt[kk][ty*8];
            float4 a1 = *(float4*)&Qt[kk][ty*8+4];
            float4 b0 = *(float4*)&Kt[kk][tx*8];
            float4 b1 = *(float4*)&Kt[kk][tx*8+4];
            float av[8] = {a0.x,a0.y,a0.z,a0.w,a1.x,a1.y,a1.z,a1.w};
            float bv[8] = {b0.x,b0.y,b0.z,b0.w,b1.x,b1.y,b1.z,b1.w};
            #pragma unroll
            for (int i = 0; i < 8; i++)
                #pragma unroll
                for (int j = 0; j < 8; j++)
                    acc[i][j] += av[i] * bv[j];
        }

        float* Pb = g_P + ((size_t)bh * NN + r0) * NN + c0;
        #pragma unroll
        for (int i = 0; i < 8; i++) {
            float4 p0, p1;
            p0.x = __expf(acc[i][0]*scale); p0.y = __expf(acc[i][1]*scale);
            p0.z = __expf(acc[i][2]*scale); p0.w = __expf(acc[i][3]*scale);
            p1.x = __expf(acc[i][4]*scale); p1.y = __expf(acc[i][5]*scale);
            p1.z = __expf(acc[i][6]*scale); p1.w = __expf(acc[i][7]*scale);
            float rs = p0.x+p0.y+p0.z+p0.w+p1.x+p1.y+p1.z+p1.w;
            // reduce over the 16 tx lanes (half-warp: same ty)
            rs += __shfl_xor_sync(0xffffffffu, rs, 1);
            rs += __shfl_xor_sync(0xffffffffu, rs, 2);
            rs += __shfl_xor_sync(0xffffffffu, rs, 4);
            rs += __shfl_xor_sync(0xffffffffu, rs, 8);
            int row = ty * 8 + i;
            if (tx == 0) s_rowsum[row] += rs;     // unique owner per row
            *(float4*)(Pb + (size_t)row * NN + tx*8)     = p0;
            *(float4*)(Pb + (size_t)row * NN + tx*8 + 4) = p1;
        }
        __syncthreads();
    }

    if (tid < 128) g_rowsum[bh * NN + r0 + tid] = s_rowsum[tid];
}

// ============================================================
// Kernel 3: t_out = diag(1/rowsum) * P * t_in ; g_acc += c_k * t_out
// grid (16 row-tiles, 32 bh), block 256, 4x4 microtile over 128x32.
// ============================================================
__global__ void pass_kernel(const float* __restrict__ coeffs, int pass) {
    const float* tin  = (pass & 1) ? g_t0 : g_t1;   // pass1: t0->t1, pass2: t1->t0, pass3: t0->t1
    float*       tout = (pass & 1) ? g_t1 : g_t0;

    const int bh = blockIdx.y;
    const int r0 = blockIdx.x * 128;
    const int h  = bh & 7;
    const float c = coeffs[h * 4 + pass];

    __shared__ float Ps[128][65];
    __shared__ float Ts[64][32];

    const int tid = threadIdx.x;
    const int cx = tid & 7;        // col group (4 cols each)
    const int ry = tid >> 3;       // row group (4 rows each), 0..31

    float acc[4][4] = {};

    const float* Prow = g_P + ((size_t)bh * NN + r0) * NN;
    const float* Tb   = tin + (size_t)bh * NN * HD;

    for (int m0 = 0; m0 < NN; m0 += 64) {
        for (int l = tid; l < 2048; l += 256) {       // 128 rows * 16 float4 along m
            int r = l >> 4, mq = l & 15;
            float4 v = *(const float4*)(Prow + (size_t)r * NN + m0 + mq * 4);
            Ps[r][mq*4+0] = v.x; Ps[r][mq*4+1] = v.y;
            Ps[r][mq*4+2] = v.z; Ps[r][mq*4+3] = v.w;
        }
        for (int l = tid; l < 512; l += 256) {        // 64 rows * 8 float4
            int mm = l >> 3, dq = l & 7;
            *(float4*)&Ts[mm][dq*4] = *(const float4*)(Tb + (size_t)(m0 + mm) * HD + dq * 4);
        }
        __syncthreads();

        #pragma unroll 8
        for (int m = 0; m < 64; m++) {
            float4 b = *(float4*)&Ts[m][cx*4];
            float p0 = Ps[ry*4+0][m];
            float p1 = Ps[ry*4+1][m];
            float p2 = Ps[ry*4+2][m];
            float p3 = Ps[ry*4+3][m];
            acc[0][0] += p0*b.x; acc[0][1] += p0*b.y; acc[0][2] += p0*b.z; acc[0][3] += p0*b.w;
            acc[1][0] += p1*b.x; acc[1][1] += p1*b.y; acc[1][2] += p1*b.z; acc[1][3] += p1*b.w;
            acc[2][0] += p2*b.x; acc[2][1] += p2*b.y; acc[2][2] += p2*b.z; acc[2][3] += p2*b.w;
            acc[3][0] += p3*b.x; acc[3][1] += p3*b.y; acc[3][2] += p3*b.z; acc[3][3] += p3*b.w;
        }
        __syncthreads();
    }

    #pragma unroll
    for (int i = 0; i < 4; i++) {
        int row = r0 + ry * 4 + i;
        float inv = 1.0f / g_rowsum[bh * NN + row];
        float4 v;
        v.x = acc[i][0] * inv; v.y = acc[i][1] * inv;
        v.z = acc[i][2] * inv; v.w = acc[i][3] * inv;
        size_t o = ((size_t)bh * NN + row) * HD + cx * 4;
        *(float4*)(tout + o) = v;
        float4 a = *(float4*)(g_acc + o);
        a.x += c * v.x; a.y += c * v.y; a.z += c * v.z; a.w += c * v.w;
        *(float4*)(g_acc + o) = a;
    }
}

// ============================================================
// Kernel 4: out = merged(g_acc) @ Wo + bo
// grid (128, 4), block 256, same tiling as kernel 1.
// ============================================================
__global__ void outproj_kernel(const float* __restrict__ Wo,
                               const float* __restrict__ bo,
                               float* __restrict__ out) {
    const int m0 = blockIdx.x * 64;
    const int c0 = blockIdx.y * 64;

    __shared__ float Ms[64][33];
    __shared__ float Ws[32][64];

    const int tid = threadIdx.x;
    const int ty = tid >> 4, tx = tid & 15;

    float acc[4][4] = {};

    for (int k0 = 0; k0 < DD; k0 += 32) {
        int hh = k0 >> 5;                 // one head per 32-wide k tile
        for (int l = tid; l < 512; l += 256) {
            int r = l >> 3, kq = l & 7;
            int m = m0 + r;
            int b_ = m >> 11, n = m & 2047;
            float4 v = *(const float4*)(g_acc + ((size_t)(b_ * HH + hh) * NN + n) * HD + kq * 4);
            Ms[r][kq*4+0] = v.x; Ms[r][kq*4+1] = v.y;
            Ms[r][kq*4+2] = v.z; Ms[r][kq*4+3] = v.w;
        }
        for (int l = tid; l < 512; l += 256) {
            int k = l >> 4, cq = l & 15;
            *(float4*)&Ws[k][cq*4] = *(const float4*)(Wo + (size_t)(k0 + k) * DD + c0 + cq * 4);
        }
        __syncthreads();
        #pragma unroll
        for (int kk = 0; kk < 32; kk++) {
            float a0 = Ms[ty*4+0][kk];
            float a1 = Ms[ty*4+1][kk];
            float a2 = Ms[ty*4+2][kk];
            float a3 = Ms[ty*4+3][kk];
            float4 b = *(float4*)&Ws[kk][tx*4];
            acc[0][0] += a0*b.x; acc[0][1] += a0*b.y; acc[0][2] += a0*b.z; acc[0][3] += a0*b.w;
            acc[1][0] += a1*b.x; acc[1][1] += a1*b.y; acc[1][2] += a1*b.z; acc[1][3] += a1*b.w;
            acc[2][0] += a2*b.x; acc[2][1] += a2*b.y; acc[2][2] += a2*b.z; acc[2][3] += a2*b.w;
            acc[3][0] += a3*b.x; acc[3][1] += a3*b.y; acc[3][2] += a3*b.z; acc[3][3] += a3*b.w;
        }
        __syncthreads();
    }

    #pragma unroll
    for (int i = 0; i < 4; i++) {
        int m = m0 + ty * 4 + i;
        #pragma unroll
        for (int j = 0; j < 4; j++) {
            int cc = c0 + tx * 4 + j;
            out[(size_t)m * DD + cc] = acc[i][j] + bo[cc];
        }
    }
}

// ============================================================
extern "C" void kernel_launch(void* const* d_in, const int* in_sizes, int n_in,
                              void* d_out, int out_size) {
    const float* x      = (const float*)d_in[0];
    const float* Wq     = (const float*)d_in[1];
    const float* bq     = (const float*)d_in[2];
    const float* Wk     = (const float*)d_in[3];
    const float* bk     = (const float*)d_in[4];
    const float* Wv     = (const float*)d_in[5];
    const float* bv     = (const float*)d_in[6];
    const float* Wo     = (const float*)d_in[7];
    const float* bo     = (const float*)d_in[8];
    const float* coeffs = (const float*)d_in[9];
    float* out = (float*)d_out;

    dim3 g1(128, 4, 3);
    qkv_kernel<<<g1, 256>>>(x, Wq, bq, Wk, bk, Wv, bv, coeffs);

    dim3 g2(16, 32);
    attnP_kernel<<<g2, 256>>>();

    pass_kernel<<<g2, 256>>>(coeffs, 1);
    pass_kernel<<<g2, 256>>>(coeffs, 2);
    pass_kernel<<<g2, 256>>>(coeffs, 3);

    dim3 g4(128, 4);
    outproj_kernel<<<g4, 256>>>(Wo, bo, out);
}